// round 7
// baseline (speedup 1.0000x reference)
#include <cuda_runtime.h>
#include <math.h>

// Problem constants (fixed by the dataset)
#define NB        8          // batch
#define C_IN      4
#define N_ETYPE   5
#define N_NTYPE   7
#define C_OUT     32
#define TEMB_CH   512
#define FAN       55         // N_ETYPE * (C_IN + N_NTYPE)
#define NMAX      400000

// Scatter accumulators:
//   g_xsum[node][et][4] : float x-sums (red.v4.f32 target)        32 MB
//   g_cnt [node][et][2] : 7 x 8-bit counters per bucket (u32 red) 16 MB
// Zero at load; gemv re-zeros what it consumes (replay invariant).
__device__ float    g_xsum[NMAX * N_ETYPE * 4];
__device__ unsigned g_cnt [NMAX * N_ETYPE * 2];
// Packed gather row: [x0,x1,x2,x3, nt(int), pad, pad, pad] = 32 B/node.
__device__ float    g_xa  [NMAX * 8];             // 12.8 MB
__device__ float    g_sw2 [NB * TEMB_CH];
__device__ float    g_inj [NB * C_OUT];

#define PREP_BLOCKS ((NMAX + 511) / 512)

// ---------------------------------------------------------------------------
// Fused kernel A: blocks [0,64) do temb lin1+lin2; blocks [64, 64+PREP) pack
// the per-node gather row g_xa (independent work, same launch).
// ---------------------------------------------------------------------------
__global__ void fusedA_kernel(const float* __restrict__ t,
                              const float* __restrict__ W1,
                              const float* __restrict__ b1,
                              const float* __restrict__ W2,
                              const float* __restrict__ b2,
                              const float* __restrict__ x,
                              const int* __restrict__ ntype, int N) {
    const int tid = threadIdx.x;
    if (blockIdx.x >= 64) {
        int n = (blockIdx.x - 64) * 512 + tid;
        if (n < N) {
            float4 xv = *reinterpret_cast<const float4*>(x + (size_t)n * C_IN);
            float* row = g_xa + (size_t)n * 8;
            *reinterpret_cast<float4*>(row) = xv;
            reinterpret_cast<int*>(row)[4] = ntype[n];
        }
        return;
    }

    __shared__ float emb[128];
    __shared__ float h1s[TEMB_CH];
    __shared__ float part[8][64];
    const int b  = blockIdx.x >> 3;
    const int bo = blockIdx.x & 7;

    if (tid < 64) {
        float f = expf(-(float)tid * (logf(10000.0f) / 63.0f));
        float ang = t[b] * f;
        emb[tid]      = sinf(ang);
        emb[tid + 64] = cosf(ang);
    }
    __syncthreads();

    {
        float s = b1[tid];
        #pragma unroll 8
        for (int i = 0; i < 128; i++) s += emb[i] * W1[i * TEMB_CH + tid];
        h1s[tid] = s * (1.0f / (1.0f + expf(-s)));
    }
    __syncthreads();

    const int cl = tid & 63;
    const int ks = tid >> 6;
    const int c  = bo * 64 + cl;
    {
        const float* h1 = h1s + ks * 64;
        const float* w  = W2 + (size_t)(ks * 64) * TEMB_CH + c;
        float s = 0.0f;
        #pragma unroll 8
        for (int i = 0; i < 64; i++) s += h1[i] * w[(size_t)i * TEMB_CH];
        part[ks][cl] = s;
    }
    __syncthreads();

    if (tid < 64) {
        float v = b2[bo * 64 + tid];
        #pragma unroll
        for (int k = 0; k < 8; k++) v += part[k][tid];
        g_sw2[b * TEMB_CH + bo * 64 + tid] = v * (1.0f / (1.0f + expf(-v)));
    }
}

// ---------------------------------------------------------------------------
// temb stage 3: inj = sw2 @ W_temb -> g_inj[b][32]. grid = 8, 256 threads.
// ---------------------------------------------------------------------------
__global__ void temb3_kernel(const float* __restrict__ Wt) {
    __shared__ float part[8][33];
    const int b  = blockIdx.x;
    const int c  = threadIdx.x & 31;
    const int ks = threadIdx.x >> 5;

    const float* sw = g_sw2 + b * TEMB_CH + ks * 64;
    const float* w  = Wt + (ks * 64) * C_OUT + c;
    float s = 0.0f;
    #pragma unroll 8
    for (int i = 0; i < 64; i++) s += sw[i] * w[i * C_OUT];
    part[ks][c] = s;
    __syncthreads();

    if (threadIdx.x < 32) {
        float v = 0.0f;
        #pragma unroll
        for (int k = 0; k < 8; k++) v += part[k][threadIdx.x];
        g_inj[b * C_OUT + threadIdx.x] = v;
    }
}

// ---------------------------------------------------------------------------
// Edge scatter, 2 edges per thread. Gather = one 32B row from g_xa.
// ---------------------------------------------------------------------------
__global__ void scatter_kernel(const int* __restrict__ ei,
                               const int* __restrict__ etype,
                               int E) {
    int e2 = (blockIdx.x * blockDim.x + threadIdx.x) * 2;
    if (e2 >= E) return;
    int2 rows = *reinterpret_cast<const int2*>(ei + e2);
    int2 cols = *reinterpret_cast<const int2*>(ei + E + e2);
    int2 ets  = *reinterpret_cast<const int2*>(etype + e2);

    const float* r0 = g_xa + (size_t)cols.x * 8;
    const float* r1 = g_xa + (size_t)cols.y * 8;
    float4 xv0 = *reinterpret_cast<const float4*>(r0);
    float4 xv1 = *reinterpret_cast<const float4*>(r1);
    int nt0 = reinterpret_cast<const int*>(r0)[4];
    int nt1 = reinterpret_cast<const int*>(r1)[4];

    size_t bk0 = (size_t)rows.x * N_ETYPE + ets.x;
    size_t bk1 = (size_t)rows.y * N_ETYPE + ets.y;

    asm volatile("red.global.add.v4.f32 [%0], {%1,%2,%3,%4};"
                 :: "l"(g_xsum + bk0 * 4), "f"(xv0.x), "f"(xv0.y), "f"(xv0.z), "f"(xv0.w)
                 : "memory");
    asm volatile("red.global.add.v4.f32 [%0], {%1,%2,%3,%4};"
                 :: "l"(g_xsum + bk1 * 4), "f"(xv1.x), "f"(xv1.y), "f"(xv1.z), "f"(xv1.w)
                 : "memory");
    atomicAdd(g_cnt + bk0 * 2 + (nt0 >> 2), 1u << ((nt0 & 3) * 8));
    atomicAdd(g_cnt + bk1 * 2 + (nt1 >> 2), 1u << ((nt1 & 3) * 8));
}

// ---------------------------------------------------------------------------
// Per-node GEMV v3: each thread handles 2 FULL nodes (all 32 channels), so a
// warp serves 64 nodes per LDS stream: warp-level LDS per node halves vs v1.
// Per j: 8 LDS.128 feed 32 FFMA2 (2 nodes x 16 pairs).
// ---------------------------------------------------------------------------
__global__ void __launch_bounds__(256, 2)
gemv_kernel(const float* __restrict__ Wc,
            const int* __restrict__ batch_id,
            float* __restrict__ out,
            int N) {
    __shared__ float Ws[FAN * C_OUT];          // pre-scaled by 0.2
    __shared__ float injs[NB * 33];
    const int tid = threadIdx.x;
    for (int i = tid; i < FAN * C_OUT; i += blockDim.x) Ws[i] = Wc[i] * 0.2f;
    if (tid < NB * C_OUT) {
        int b = tid >> 5, c = tid & 31;
        injs[b * 33 + c] = g_inj[tid];
    }
    __syncthreads();

    int n0 = (blockIdx.x * blockDim.x + tid) * 2;
    if (n0 >= N) return;

    unsigned long long acc0[16], acc1[16];
    #pragma unroll
    for (int k = 0; k < 16; k++) { acc0[k] = 0ULL; acc1[k] = 0ULL; }

    float*    xp = g_xsum + (size_t)n0 * (N_ETYPE * 4);
    unsigned* cp = g_cnt  + (size_t)n0 * (N_ETYPE * 2);

    #pragma unroll
    for (int et = 0; et < N_ETYPE; et++) {
        float4 v0 = *reinterpret_cast<float4*>(xp + et * 4);
        float4 v1 = *reinterpret_cast<float4*>(xp + N_ETYPE * 4 + et * 4);
        uint2  c0 = *reinterpret_cast<uint2*>(cp + et * 2);
        uint2  c1 = *reinterpret_cast<uint2*>(cp + N_ETYPE * 2 + et * 2);
        float a0[11], a1[11];
        a0[0] = v0.x; a0[1] = v0.y; a0[2] = v0.z; a0[3] = v0.w;
        a0[4]  = (float)( c0.x        & 0xFFu);
        a0[5]  = (float)((c0.x >>  8) & 0xFFu);
        a0[6]  = (float)((c0.x >> 16) & 0xFFu);
        a0[7]  = (float)( c0.x >> 24);
        a0[8]  = (float)( c0.y        & 0xFFu);
        a0[9]  = (float)((c0.y >>  8) & 0xFFu);
        a0[10] = (float)((c0.y >> 16) & 0xFFu);
        a1[0] = v1.x; a1[1] = v1.y; a1[2] = v1.z; a1[3] = v1.w;
        a1[4]  = (float)( c1.x        & 0xFFu);
        a1[5]  = (float)((c1.x >>  8) & 0xFFu);
        a1[6]  = (float)((c1.x >> 16) & 0xFFu);
        a1[7]  = (float)( c1.x >> 24);
        a1[8]  = (float)( c1.y        & 0xFFu);
        a1[9]  = (float)((c1.y >>  8) & 0xFFu);
        a1[10] = (float)((c1.y >> 16) & 0xFFu);

        #pragma unroll
        for (int j = 0; j < 11; j++) {
            const float4* Wv =
                reinterpret_cast<const float4*>(&Ws[(et * 11 + j) * C_OUT]);
            unsigned long long av0, av1;
            asm("mov.b64 %0, {%1, %1};" : "=l"(av0) : "f"(a0[j]));
            asm("mov.b64 %0, {%1, %1};" : "=l"(av1) : "f"(a1[j]));
            #pragma unroll
            for (int k4 = 0; k4 < 8; k4++) {
                float4 wq = Wv[k4];                 // one LDS.128
                unsigned long long wlo, whi;
                asm("mov.b64 %0, {%1, %2};" : "=l"(wlo) : "f"(wq.x), "f"(wq.y));
                asm("mov.b64 %0, {%1, %2};" : "=l"(whi) : "f"(wq.z), "f"(wq.w));
                asm("fma.rn.f32x2 %0, %1, %2, %0;"
                    : "+l"(acc0[2 * k4 + 0]) : "l"(av0), "l"(wlo));
                asm("fma.rn.f32x2 %0, %1, %2, %0;"
                    : "+l"(acc0[2 * k4 + 1]) : "l"(av0), "l"(whi));
                asm("fma.rn.f32x2 %0, %1, %2, %0;"
                    : "+l"(acc1[2 * k4 + 0]) : "l"(av1), "l"(wlo));
                asm("fma.rn.f32x2 %0, %1, %2, %0;"
                    : "+l"(acc1[2 * k4 + 1]) : "l"(av1), "l"(whi));
            }
        }
    }

    int2 bb = *reinterpret_cast<const int2*>(batch_id + n0);
    const float* iv0 = &injs[bb.x * 33];
    const float* iv1 = &injs[bb.y * 33];
    float* op0 = out + (size_t)n0 * C_OUT;
    float* op1 = op0 + C_OUT;
    #pragma unroll
    for (int k = 0; k < 16; k += 2) {
        float l0, h0, l1, h1;
        asm("mov.b64 {%0, %1}, %2;" : "=f"(l0), "=f"(h0) : "l"(acc0[k]));
        asm("mov.b64 {%0, %1}, %2;" : "=f"(l1), "=f"(h1) : "l"(acc0[k + 1]));
        float4 o; o.x = l0 + iv0[2*k]; o.y = h0 + iv0[2*k+1];
        o.z = l1 + iv0[2*k+2]; o.w = h1 + iv0[2*k+3];
        *reinterpret_cast<float4*>(op0 + 2 * k) = o;
        asm("mov.b64 {%0, %1}, %2;" : "=f"(l0), "=f"(h0) : "l"(acc1[k]));
        asm("mov.b64 {%0, %1}, %2;" : "=f"(l1), "=f"(h1) : "l"(acc1[k + 1]));
        float4 p; p.x = l0 + iv1[2*k]; p.y = h0 + iv1[2*k+1];
        p.z = l1 + iv1[2*k+2]; p.w = h1 + iv1[2*k+3];
        *reinterpret_cast<float4*>(op1 + 2 * k) = p;
    }

    // Re-zero both nodes' accumulators (coalesced vector stores).
    float4 z4 = make_float4(0.f, 0.f, 0.f, 0.f);
    #pragma unroll
    for (int i = 0; i < 2 * N_ETYPE; i++)
        *reinterpret_cast<float4*>(xp + i * 4) = z4;
    uint4 z2 = make_uint4(0u, 0u, 0u, 0u);
    #pragma unroll
    for (int i = 0; i < N_ETYPE; i++)          // 2 nodes x 40B = 5 x 16B
        *reinterpret_cast<uint4*>(cp + i * 4) = z2;
}

// ---------------------------------------------------------------------------
// Inputs (metadata order):
//  0 x [N,4] f32        1 t [8] f32          2 edge_index [2,E] i32
//  3 edge_type [E] i32  4 node_type [N] i32  5 batch_id [N] i32
//  6 W_conv [55,32] f32 7 W1 [128,512]       8 b1 [512]
//  9 W2 [512,512]      10 b2 [512]          11 W_temb [512,32]
// Output: [N,32] f32
// ---------------------------------------------------------------------------
extern "C" void kernel_launch(void* const* d_in, const int* in_sizes, int n_in,
                              void* d_out, int out_size) {
    const float* x        = (const float*)d_in[0];
    const float* t        = (const float*)d_in[1];
    const int*   ei       = (const int*)d_in[2];
    const int*   etype    = (const int*)d_in[3];
    const int*   ntype    = (const int*)d_in[4];
    const int*   batch_id = (const int*)d_in[5];
    const float* W_conv   = (const float*)d_in[6];
    const float* W1       = (const float*)d_in[7];
    const float* b1       = (const float*)d_in[8];
    const float* W2       = (const float*)d_in[9];
    const float* b2       = (const float*)d_in[10];
    const float* W_temb   = (const float*)d_in[11];
    float* out = (float*)d_out;

    const int E = in_sizes[3];
    const int N = in_sizes[4];
    const int prep_blocks = (N + 511) / 512;

    fusedA_kernel<<<64 + prep_blocks, 512>>>(t, W1, b1, W2, b2, x, ntype, N);
    temb3_kernel<<<NB, 256>>>(W_temb);
    scatter_kernel<<<(E / 2 + 255) / 256, 256>>>(ei, etype, E);
    gemv_kernel<<<(N / 2 + 255) / 256, 256>>>(W_conv, batch_id, out, N); // slot 4
}

// round 8
// speedup vs baseline: 1.0186x; 1.0186x over previous
#include <cuda_runtime.h>
#include <math.h>

// Problem constants (fixed by the dataset)
#define NB        8          // batch
#define C_IN      4
#define N_ETYPE   5
#define N_NTYPE   7
#define C_OUT     32
#define TEMB_CH   512
#define FAN       55         // N_ETYPE * (C_IN + N_NTYPE)
#define NMAX      400000

// Scatter accumulators:
//   g_xsum[node][et][4] : float x-sums (red.v4.f32 target)        32 MB
//   g_cnt [node][et][2] : 7 x 8-bit counters per bucket (u32 red) 16 MB
// Zero at load; gemv re-zeros what it consumes (replay invariant).
__device__ float    g_xsum[NMAX * N_ETYPE * 4];
__device__ unsigned g_cnt [NMAX * N_ETYPE * 2];
// Packed gather row: [x0,x1,x2,x3, nt(int), pad, pad, pad] = 32 B/node.
__device__ float    g_xa  [NMAX * 8];             // 12.8 MB
__device__ float    g_sw2 [NB * TEMB_CH];
__device__ float    g_inj [NB * C_OUT];

// ---------------------------------------------------------------------------
// Fused kernel A: blocks [0,64) do temb lin1+lin2; blocks [64, 64+PREP) pack
// the per-node gather row g_xa (independent work, same launch).
// ---------------------------------------------------------------------------
__global__ void fusedA_kernel(const float* __restrict__ t,
                              const float* __restrict__ W1,
                              const float* __restrict__ b1,
                              const float* __restrict__ W2,
                              const float* __restrict__ b2,
                              const float* __restrict__ x,
                              const int* __restrict__ ntype, int N) {
    const int tid = threadIdx.x;
    if (blockIdx.x >= 64) {
        int n = (blockIdx.x - 64) * 512 + tid;
        if (n < N) {
            float4 xv = *reinterpret_cast<const float4*>(x + (size_t)n * C_IN);
            float* row = g_xa + (size_t)n * 8;
            *reinterpret_cast<float4*>(row) = xv;
            reinterpret_cast<int*>(row)[4] = ntype[n];
        }
        return;
    }

    __shared__ float emb[128];
    __shared__ float h1s[TEMB_CH];
    __shared__ float part[8][64];
    const int b  = blockIdx.x >> 3;
    const int bo = blockIdx.x & 7;

    if (tid < 64) {
        float f = expf(-(float)tid * (logf(10000.0f) / 63.0f));
        float ang = t[b] * f;
        emb[tid]      = sinf(ang);
        emb[tid + 64] = cosf(ang);
    }
    __syncthreads();

    {
        float s = b1[tid];
        #pragma unroll 8
        for (int i = 0; i < 128; i++) s += emb[i] * W1[i * TEMB_CH + tid];
        h1s[tid] = s * (1.0f / (1.0f + expf(-s)));
    }
    __syncthreads();

    const int cl = tid & 63;
    const int ks = tid >> 6;
    const int c  = bo * 64 + cl;
    {
        const float* h1 = h1s + ks * 64;
        const float* w  = W2 + (size_t)(ks * 64) * TEMB_CH + c;
        float s = 0.0f;
        #pragma unroll 8
        for (int i = 0; i < 64; i++) s += h1[i] * w[(size_t)i * TEMB_CH];
        part[ks][cl] = s;
    }
    __syncthreads();

    if (tid < 64) {
        float v = b2[bo * 64 + tid];
        #pragma unroll
        for (int k = 0; k < 8; k++) v += part[k][tid];
        g_sw2[b * TEMB_CH + bo * 64 + tid] = v * (1.0f / (1.0f + expf(-v)));
    }
}

// ---------------------------------------------------------------------------
// temb stage 3: inj = sw2 @ W_temb -> g_inj[b][32]. grid = 8, 256 threads.
// ---------------------------------------------------------------------------
__global__ void temb3_kernel(const float* __restrict__ Wt) {
    __shared__ float part[8][33];
    const int b  = blockIdx.x;
    const int c  = threadIdx.x & 31;
    const int ks = threadIdx.x >> 5;

    const float* sw = g_sw2 + b * TEMB_CH + ks * 64;
    const float* w  = Wt + (ks * 64) * C_OUT + c;
    float s = 0.0f;
    #pragma unroll 8
    for (int i = 0; i < 64; i++) s += sw[i] * w[i * C_OUT];
    part[ks][c] = s;
    __syncthreads();

    if (threadIdx.x < 32) {
        float v = 0.0f;
        #pragma unroll
        for (int k = 0; k < 8; k++) v += part[k][threadIdx.x];
        g_inj[b * C_OUT + threadIdx.x] = v;
    }
}

// ---------------------------------------------------------------------------
// Edge scatter, 2 edges per thread. Gather = one 32B row from g_xa.
// ---------------------------------------------------------------------------
__global__ void scatter_kernel(const int* __restrict__ ei,
                               const int* __restrict__ etype,
                               int E) {
    int e2 = (blockIdx.x * blockDim.x + threadIdx.x) * 2;
    if (e2 >= E) return;
    int2 rows = *reinterpret_cast<const int2*>(ei + e2);
    int2 cols = *reinterpret_cast<const int2*>(ei + E + e2);
    int2 ets  = *reinterpret_cast<const int2*>(etype + e2);

    const float* r0 = g_xa + (size_t)cols.x * 8;
    const float* r1 = g_xa + (size_t)cols.y * 8;
    float4 xv0 = *reinterpret_cast<const float4*>(r0);
    float4 xv1 = *reinterpret_cast<const float4*>(r1);
    int nt0 = reinterpret_cast<const int*>(r0)[4];
    int nt1 = reinterpret_cast<const int*>(r1)[4];

    size_t bk0 = (size_t)rows.x * N_ETYPE + ets.x;
    size_t bk1 = (size_t)rows.y * N_ETYPE + ets.y;

    asm volatile("red.global.add.v4.f32 [%0], {%1,%2,%3,%4};"
                 :: "l"(g_xsum + bk0 * 4), "f"(xv0.x), "f"(xv0.y), "f"(xv0.z), "f"(xv0.w)
                 : "memory");
    asm volatile("red.global.add.v4.f32 [%0], {%1,%2,%3,%4};"
                 :: "l"(g_xsum + bk1 * 4), "f"(xv1.x), "f"(xv1.y), "f"(xv1.z), "f"(xv1.w)
                 : "memory");
    atomicAdd(g_cnt + bk0 * 2 + (nt0 >> 2), 1u << ((nt0 & 3) * 8));
    atomicAdd(g_cnt + bk1 * 2 + (nt1 >> 2), 1u << ((nt1 & 3) * 8));
}

// ---------------------------------------------------------------------------
// Per-node GEMV v4: 2 full nodes per thread; weights loaded as ulonglong2
// (one LDS.128 = two ready 64-bit FFMA2 operands, NO mov.b64 packing).
// Per j: 8 LDS.128 feed 32 FFMA2.
// ---------------------------------------------------------------------------
__global__ void __launch_bounds__(256, 2)
gemv_kernel(const float* __restrict__ Wc,
            const int* __restrict__ batch_id,
            float* __restrict__ out,
            int N) {
    __shared__ __align__(16) float Ws[FAN * C_OUT];   // pre-scaled by 0.2
    __shared__ float injs[NB * 33];
    const int tid = threadIdx.x;
    for (int i = tid; i < FAN * C_OUT; i += blockDim.x) Ws[i] = Wc[i] * 0.2f;
    if (tid < NB * C_OUT) {
        int b = tid >> 5, c = tid & 31;
        injs[b * 33 + c] = g_inj[tid];
    }
    __syncthreads();

    int n0 = (blockIdx.x * blockDim.x + tid) * 2;
    if (n0 >= N) return;

    unsigned long long acc0[16], acc1[16];
    #pragma unroll
    for (int k = 0; k < 16; k++) { acc0[k] = 0ULL; acc1[k] = 0ULL; }

    float*    xp = g_xsum + (size_t)n0 * (N_ETYPE * 4);
    unsigned* cp = g_cnt  + (size_t)n0 * (N_ETYPE * 2);

    #pragma unroll
    for (int et = 0; et < N_ETYPE; et++) {
        float4 v0 = *reinterpret_cast<float4*>(xp + et * 4);
        float4 v1 = *reinterpret_cast<float4*>(xp + N_ETYPE * 4 + et * 4);
        uint2  c0 = *reinterpret_cast<uint2*>(cp + et * 2);
        uint2  c1 = *reinterpret_cast<uint2*>(cp + N_ETYPE * 2 + et * 2);
        float a0[11], a1[11];
        a0[0] = v0.x; a0[1] = v0.y; a0[2] = v0.z; a0[3] = v0.w;
        a0[4]  = (float)( c0.x        & 0xFFu);
        a0[5]  = (float)((c0.x >>  8) & 0xFFu);
        a0[6]  = (float)((c0.x >> 16) & 0xFFu);
        a0[7]  = (float)( c0.x >> 24);
        a0[8]  = (float)( c0.y        & 0xFFu);
        a0[9]  = (float)((c0.y >>  8) & 0xFFu);
        a0[10] = (float)((c0.y >> 16) & 0xFFu);
        a1[0] = v1.x; a1[1] = v1.y; a1[2] = v1.z; a1[3] = v1.w;
        a1[4]  = (float)( c1.x        & 0xFFu);
        a1[5]  = (float)((c1.x >>  8) & 0xFFu);
        a1[6]  = (float)((c1.x >> 16) & 0xFFu);
        a1[7]  = (float)( c1.x >> 24);
        a1[8]  = (float)( c1.y        & 0xFFu);
        a1[9]  = (float)((c1.y >>  8) & 0xFFu);
        a1[10] = (float)((c1.y >> 16) & 0xFFu);

        #pragma unroll
        for (int j = 0; j < 11; j++) {
            const ulonglong2* Wv =
                reinterpret_cast<const ulonglong2*>(&Ws[(et * 11 + j) * C_OUT]);
            unsigned long long av0, av1;
            asm("mov.b64 %0, {%1, %1};" : "=l"(av0) : "f"(a0[j]));
            asm("mov.b64 %0, {%1, %1};" : "=l"(av1) : "f"(a1[j]));
            #pragma unroll
            for (int q = 0; q < 8; q++) {
                ulonglong2 w = Wv[q];               // one LDS.128, two u64 operands
                asm("fma.rn.f32x2 %0, %1, %2, %0;"
                    : "+l"(acc0[2 * q + 0]) : "l"(av0), "l"(w.x));
                asm("fma.rn.f32x2 %0, %1, %2, %0;"
                    : "+l"(acc0[2 * q + 1]) : "l"(av0), "l"(w.y));
                asm("fma.rn.f32x2 %0, %1, %2, %0;"
                    : "+l"(acc1[2 * q + 0]) : "l"(av1), "l"(w.x));
                asm("fma.rn.f32x2 %0, %1, %2, %0;"
                    : "+l"(acc1[2 * q + 1]) : "l"(av1), "l"(w.y));
            }
        }
    }

    int2 bb = *reinterpret_cast<const int2*>(batch_id + n0);
    const float* iv0 = &injs[bb.x * 33];
    const float* iv1 = &injs[bb.y * 33];
    float* op0 = out + (size_t)n0 * C_OUT;
    float* op1 = op0 + C_OUT;
    #pragma unroll
    for (int k = 0; k < 16; k += 2) {
        float l0, h0, l1, h1;
        asm("mov.b64 {%0, %1}, %2;" : "=f"(l0), "=f"(h0) : "l"(acc0[k]));
        asm("mov.b64 {%0, %1}, %2;" : "=f"(l1), "=f"(h1) : "l"(acc0[k + 1]));
        float4 o; o.x = l0 + iv0[2*k]; o.y = h0 + iv0[2*k+1];
        o.z = l1 + iv0[2*k+2]; o.w = h1 + iv0[2*k+3];
        *reinterpret_cast<float4*>(op0 + 2 * k) = o;
        asm("mov.b64 {%0, %1}, %2;" : "=f"(l0), "=f"(h0) : "l"(acc1[k]));
        asm("mov.b64 {%0, %1}, %2;" : "=f"(l1), "=f"(h1) : "l"(acc1[k + 1]));
        float4 p; p.x = l0 + iv1[2*k]; p.y = h0 + iv1[2*k+1];
        p.z = l1 + iv1[2*k+2]; p.w = h1 + iv1[2*k+3];
        *reinterpret_cast<float4*>(op1 + 2 * k) = p;
    }

    // Re-zero both nodes' accumulators (coalesced vector stores).
    float4 z4 = make_float4(0.f, 0.f, 0.f, 0.f);
    #pragma unroll
    for (int i = 0; i < 2 * N_ETYPE; i++)
        *reinterpret_cast<float4*>(xp + i * 4) = z4;
    uint4 z2 = make_uint4(0u, 0u, 0u, 0u);
    #pragma unroll
    for (int i = 0; i < N_ETYPE; i++)          // 2 nodes x 40B = 5 x 16B
        *reinterpret_cast<uint4*>(cp + i * 4) = z2;
}

// ---------------------------------------------------------------------------
// Inputs (metadata order):
//  0 x [N,4] f32        1 t [8] f32          2 edge_index [2,E] i32
//  3 edge_type [E] i32  4 node_type [N] i32  5 batch_id [N] i32
//  6 W_conv [55,32] f32 7 W1 [128,512]       8 b1 [512]
//  9 W2 [512,512]      10 b2 [512]          11 W_temb [512,32]
// Output: [N,32] f32
// ---------------------------------------------------------------------------
extern "C" void kernel_launch(void* const* d_in, const int* in_sizes, int n_in,
                              void* d_out, int out_size) {
    const float* x        = (const float*)d_in[0];
    const float* t        = (const float*)d_in[1];
    const int*   ei       = (const int*)d_in[2];
    const int*   etype    = (const int*)d_in[3];
    const int*   ntype    = (const int*)d_in[4];
    const int*   batch_id = (const int*)d_in[5];
    const float* W_conv   = (const float*)d_in[6];
    const float* W1       = (const float*)d_in[7];
    const float* b1       = (const float*)d_in[8];
    const float* W2       = (const float*)d_in[9];
    const float* b2       = (const float*)d_in[10];
    const float* W_temb   = (const float*)d_in[11];
    float* out = (float*)d_out;

    const int E = in_sizes[3];
    const int N = in_sizes[4];
    const int prep_blocks = (N + 511) / 512;

    fusedA_kernel<<<64 + prep_blocks, 512>>>(t, W1, b1, W2, b2, x, ntype, N);
    scatter_kernel<<<(E / 2 + 255) / 256, 256>>>(ei, etype, E);
    temb3_kernel<<<NB, 256>>>(W_temb);
    gemv_kernel<<<(N / 2 + 255) / 256, 256>>>(W_conv, batch_id, out, N); // slot 4
}

// round 9
// speedup vs baseline: 1.0872x; 1.0674x over previous
#include <cuda_runtime.h>
#include <math.h>

// Problem constants (fixed by the dataset)
#define NB        8          // batch
#define C_IN      4
#define N_ETYPE   5
#define N_NTYPE   7
#define C_OUT     32
#define TEMB_CH   512
#define FAN       55         // N_ETYPE * (C_IN + N_NTYPE)
#define NMAX      400000

// Scatter accumulators:
//   g_xsum[node][et][4] : float x-sums (red.v4.f32 target)        32 MB
//   g_cnt [node][et][2] : 7 x 8-bit counters per bucket (u32 red) 16 MB
// Zero at load; gemv re-zeros what it consumes (replay invariant).
__device__ float    g_xsum[NMAX * N_ETYPE * 4];
__device__ unsigned g_cnt [NMAX * N_ETYPE * 2];
// Packed gather row: [x0,x1,x2,x3, nt(int), pad, pad, pad] = 32 B/node.
__device__ float    g_xa  [NMAX * 8];             // 12.8 MB
__device__ float    g_sw2 [NB * TEMB_CH];
__device__ float    g_inj [NB * C_OUT];

// ---------------------------------------------------------------------------
// Fused kernel A: blocks [0,64) do temb lin1+lin2; blocks [64, 64+PREP) pack
// the per-node gather row g_xa (independent work, same launch).
// ---------------------------------------------------------------------------
__global__ void fusedA_kernel(const float* __restrict__ t,
                              const float* __restrict__ W1,
                              const float* __restrict__ b1,
                              const float* __restrict__ W2,
                              const float* __restrict__ b2,
                              const float* __restrict__ x,
                              const int* __restrict__ ntype, int N) {
    const int tid = threadIdx.x;
    if (blockIdx.x >= 64) {
        int n = (blockIdx.x - 64) * 512 + tid;
        if (n < N) {
            float4 xv = *reinterpret_cast<const float4*>(x + (size_t)n * C_IN);
            float* row = g_xa + (size_t)n * 8;
            *reinterpret_cast<float4*>(row) = xv;
            reinterpret_cast<int*>(row)[4] = ntype[n];
        }
        return;
    }

    __shared__ float emb[128];
    __shared__ float h1s[TEMB_CH];
    __shared__ float part[8][64];
    const int b  = blockIdx.x >> 3;
    const int bo = blockIdx.x & 7;

    if (tid < 64) {
        float f = expf(-(float)tid * (logf(10000.0f) / 63.0f));
        float ang = t[b] * f;
        emb[tid]      = sinf(ang);
        emb[tid + 64] = cosf(ang);
    }
    __syncthreads();

    {
        float s = b1[tid];
        #pragma unroll 8
        for (int i = 0; i < 128; i++) s += emb[i] * W1[i * TEMB_CH + tid];
        h1s[tid] = s * (1.0f / (1.0f + expf(-s)));
    }
    __syncthreads();

    const int cl = tid & 63;
    const int ks = tid >> 6;
    const int c  = bo * 64 + cl;
    {
        const float* h1 = h1s + ks * 64;
        const float* w  = W2 + (size_t)(ks * 64) * TEMB_CH + c;
        float s = 0.0f;
        #pragma unroll 8
        for (int i = 0; i < 64; i++) s += h1[i] * w[(size_t)i * TEMB_CH];
        part[ks][cl] = s;
    }
    __syncthreads();

    if (tid < 64) {
        float v = b2[bo * 64 + tid];
        #pragma unroll
        for (int k = 0; k < 8; k++) v += part[k][tid];
        g_sw2[b * TEMB_CH + bo * 64 + tid] = v * (1.0f / (1.0f + expf(-v)));
    }
}

// ---------------------------------------------------------------------------
// Fused kernel B: blocks [0,8) compute inj = sw2 @ W_temb (temb stage 3);
// blocks [8, ...) scatter edges (2 per thread, gather = 32B row of g_xa).
// ---------------------------------------------------------------------------
__global__ void scatterB_kernel(const int* __restrict__ ei,
                                const int* __restrict__ etype,
                                const float* __restrict__ Wt,
                                int E) {
    const int tid = threadIdx.x;
    if (blockIdx.x < 8) {
        __shared__ float part[8][33];
        const int b  = blockIdx.x;
        const int c  = tid & 31;
        const int ks = tid >> 5;

        const float* sw = g_sw2 + b * TEMB_CH + ks * 64;
        const float* w  = Wt + (ks * 64) * C_OUT + c;
        float s = 0.0f;
        #pragma unroll 8
        for (int i = 0; i < 64; i++) s += sw[i] * w[i * C_OUT];
        part[ks][c] = s;
        __syncthreads();

        if (tid < 32) {
            float v = 0.0f;
            #pragma unroll
            for (int k = 0; k < 8; k++) v += part[k][tid];
            g_inj[b * C_OUT + tid] = v;
        }
        return;
    }

    int e2 = ((blockIdx.x - 8) * blockDim.x + tid) * 2;
    if (e2 >= E) return;
    int2 rows = *reinterpret_cast<const int2*>(ei + e2);
    int2 cols = *reinterpret_cast<const int2*>(ei + E + e2);
    int2 ets  = *reinterpret_cast<const int2*>(etype + e2);

    const float* r0 = g_xa + (size_t)cols.x * 8;
    const float* r1 = g_xa + (size_t)cols.y * 8;
    float4 xv0 = *reinterpret_cast<const float4*>(r0);
    float4 xv1 = *reinterpret_cast<const float4*>(r1);
    int nt0 = reinterpret_cast<const int*>(r0)[4];
    int nt1 = reinterpret_cast<const int*>(r1)[4];

    size_t bk0 = (size_t)rows.x * N_ETYPE + ets.x;
    size_t bk1 = (size_t)rows.y * N_ETYPE + ets.y;

    asm volatile("red.global.add.v4.f32 [%0], {%1,%2,%3,%4};"
                 :: "l"(g_xsum + bk0 * 4), "f"(xv0.x), "f"(xv0.y), "f"(xv0.z), "f"(xv0.w)
                 : "memory");
    asm volatile("red.global.add.v4.f32 [%0], {%1,%2,%3,%4};"
                 :: "l"(g_xsum + bk1 * 4), "f"(xv1.x), "f"(xv1.y), "f"(xv1.z), "f"(xv1.w)
                 : "memory");
    atomicAdd(g_cnt + bk0 * 2 + (nt0 >> 2), 1u << ((nt0 & 3) * 8));
    atomicAdd(g_cnt + bk1 * 2 + (nt1 >> 2), 1u << ((nt1 & 3) * 8));
}

// ---------------------------------------------------------------------------
// u8 counter -> exact fp32 via PRMT magic number (no I2F, no mask chains):
// places byte k of w into the mantissa of 2^23, then exact FSUB.
// ---------------------------------------------------------------------------
template <int K>
__device__ __forceinline__ float byte2f(unsigned w) {
    unsigned r;
    asm("prmt.b32 %0, %1, %2, %3;"
        : "=r"(r) : "r"(w), "r"(0x4B000000u), "n"(0x7540u | K));
    return __uint_as_float(r) - 8388608.0f;
}

// ---------------------------------------------------------------------------
// Per-node GEMV v6: 2 full nodes per thread; weights as ulonglong2 from smem;
// counts converted with PRMT+FSUB; 128-thread blocks, 5 blocks/SM target.
// ---------------------------------------------------------------------------
__global__ void __launch_bounds__(128, 5)
gemv_kernel(const float* __restrict__ Wc,
            const int* __restrict__ batch_id,
            float* __restrict__ out,
            int N) {
    __shared__ __align__(16) float Ws[FAN * C_OUT];   // pre-scaled by 0.2
    __shared__ float injs[NB * 33];
    const int tid = threadIdx.x;
    for (int i = tid; i < FAN * C_OUT; i += blockDim.x) Ws[i] = Wc[i] * 0.2f;
    for (int i = tid; i < NB * C_OUT; i += blockDim.x) {
        int b = i >> 5, c = i & 31;
        injs[b * 33 + c] = g_inj[i];
    }
    __syncthreads();

    int n0 = (blockIdx.x * blockDim.x + tid) * 2;
    if (n0 >= N) return;

    unsigned long long acc0[16], acc1[16];
    #pragma unroll
    for (int k = 0; k < 16; k++) { acc0[k] = 0ULL; acc1[k] = 0ULL; }

    float*    xp = g_xsum + (size_t)n0 * (N_ETYPE * 4);
    unsigned* cp = g_cnt  + (size_t)n0 * (N_ETYPE * 2);

    // Load both nodes' counters with 3 vector loads each (40B contiguous).
    unsigned cA[10], cB[10];
    {
        uint4 a0 = *reinterpret_cast<uint4*>(cp);
        uint4 a1 = *reinterpret_cast<uint4*>(cp + 4);
        uint2 a2 = *reinterpret_cast<uint2*>(cp + 8);
        cA[0]=a0.x; cA[1]=a0.y; cA[2]=a0.z; cA[3]=a0.w;
        cA[4]=a1.x; cA[5]=a1.y; cA[6]=a1.z; cA[7]=a1.w;
        cA[8]=a2.x; cA[9]=a2.y;
        uint4 b0 = *reinterpret_cast<uint4*>(cp + 10);
        uint4 b1 = *reinterpret_cast<uint4*>(cp + 14);
        uint2 b2 = *reinterpret_cast<uint2*>(cp + 18);
        cB[0]=b0.x; cB[1]=b0.y; cB[2]=b0.z; cB[3]=b0.w;
        cB[4]=b1.x; cB[5]=b1.y; cB[6]=b1.z; cB[7]=b1.w;
        cB[8]=b2.x; cB[9]=b2.y;
    }

    #pragma unroll
    for (int et = 0; et < N_ETYPE; et++) {
        float4 v0 = *reinterpret_cast<float4*>(xp + et * 4);
        float4 v1 = *reinterpret_cast<float4*>(xp + N_ETYPE * 4 + et * 4);
        unsigned lo0 = cA[et * 2], hi0 = cA[et * 2 + 1];
        unsigned lo1 = cB[et * 2], hi1 = cB[et * 2 + 1];
        float a0[11], a1[11];
        a0[0] = v0.x; a0[1] = v0.y; a0[2] = v0.z; a0[3] = v0.w;
        a0[4] = byte2f<0>(lo0); a0[5] = byte2f<1>(lo0);
        a0[6] = byte2f<2>(lo0); a0[7] = byte2f<3>(lo0);
        a0[8] = byte2f<0>(hi0); a0[9] = byte2f<1>(hi0);
        a0[10] = byte2f<2>(hi0);
        a1[0] = v1.x; a1[1] = v1.y; a1[2] = v1.z; a1[3] = v1.w;
        a1[4] = byte2f<0>(lo1); a1[5] = byte2f<1>(lo1);
        a1[6] = byte2f<2>(lo1); a1[7] = byte2f<3>(lo1);
        a1[8] = byte2f<0>(hi1); a1[9] = byte2f<1>(hi1);
        a1[10] = byte2f<2>(hi1);

        #pragma unroll
        for (int j = 0; j < 11; j++) {
            const ulonglong2* Wv =
                reinterpret_cast<const ulonglong2*>(&Ws[(et * 11 + j) * C_OUT]);
            unsigned long long av0, av1;
            asm("mov.b64 %0, {%1, %1};" : "=l"(av0) : "f"(a0[j]));
            asm("mov.b64 %0, {%1, %1};" : "=l"(av1) : "f"(a1[j]));
            #pragma unroll
            for (int q = 0; q < 8; q++) {
                ulonglong2 w = Wv[q];               // one LDS.128, two u64 operands
                asm("fma.rn.f32x2 %0, %1, %2, %0;"
                    : "+l"(acc0[2 * q + 0]) : "l"(av0), "l"(w.x));
                asm("fma.rn.f32x2 %0, %1, %2, %0;"
                    : "+l"(acc0[2 * q + 1]) : "l"(av0), "l"(w.y));
                asm("fma.rn.f32x2 %0, %1, %2, %0;"
                    : "+l"(acc1[2 * q + 0]) : "l"(av1), "l"(w.x));
                asm("fma.rn.f32x2 %0, %1, %2, %0;"
                    : "+l"(acc1[2 * q + 1]) : "l"(av1), "l"(w.y));
            }
        }
    }

    int2 bb = *reinterpret_cast<const int2*>(batch_id + n0);
    const float* iv0 = &injs[bb.x * 33];
    const float* iv1 = &injs[bb.y * 33];
    float* op0 = out + (size_t)n0 * C_OUT;
    float* op1 = op0 + C_OUT;
    #pragma unroll
    for (int k = 0; k < 16; k += 2) {
        float l0, h0, l1, h1;
        asm("mov.b64 {%0, %1}, %2;" : "=f"(l0), "=f"(h0) : "l"(acc0[k]));
        asm("mov.b64 {%0, %1}, %2;" : "=f"(l1), "=f"(h1) : "l"(acc0[k + 1]));
        float4 o; o.x = l0 + iv0[2*k]; o.y = h0 + iv0[2*k+1];
        o.z = l1 + iv0[2*k+2]; o.w = h1 + iv0[2*k+3];
        *reinterpret_cast<float4*>(op0 + 2 * k) = o;
        asm("mov.b64 {%0, %1}, %2;" : "=f"(l0), "=f"(h0) : "l"(acc1[k]));
        asm("mov.b64 {%0, %1}, %2;" : "=f"(l1), "=f"(h1) : "l"(acc1[k + 1]));
        float4 p; p.x = l0 + iv1[2*k]; p.y = h0 + iv1[2*k+1];
        p.z = l1 + iv1[2*k+2]; p.w = h1 + iv1[2*k+3];
        *reinterpret_cast<float4*>(op1 + 2 * k) = p;
    }

    // Re-zero both nodes' accumulators (coalesced vector stores).
    float4 z4 = make_float4(0.f, 0.f, 0.f, 0.f);
    #pragma unroll
    for (int i = 0; i < 2 * N_ETYPE; i++)
        *reinterpret_cast<float4*>(xp + i * 4) = z4;
    uint4 z2 = make_uint4(0u, 0u, 0u, 0u);
    #pragma unroll
    for (int i = 0; i < N_ETYPE; i++)          // 2 nodes x 40B = 5 x 16B
        *reinterpret_cast<uint4*>(cp + i * 4) = z2;
}

// ---------------------------------------------------------------------------
// Inputs (metadata order):
//  0 x [N,4] f32        1 t [8] f32          2 edge_index [2,E] i32
//  3 edge_type [E] i32  4 node_type [N] i32  5 batch_id [N] i32
//  6 W_conv [55,32] f32 7 W1 [128,512]       8 b1 [512]
//  9 W2 [512,512]      10 b2 [512]          11 W_temb [512,32]
// Output: [N,32] f32
// ---------------------------------------------------------------------------
extern "C" void kernel_launch(void* const* d_in, const int* in_sizes, int n_in,
                              void* d_out, int out_size) {
    const float* x        = (const float*)d_in[0];
    const float* t        = (const float*)d_in[1];
    const int*   ei       = (const int*)d_in[2];
    const int*   etype    = (const int*)d_in[3];
    const int*   ntype    = (const int*)d_in[4];
    const int*   batch_id = (const int*)d_in[5];
    const float* W_conv   = (const float*)d_in[6];
    const float* W1       = (const float*)d_in[7];
    const float* b1       = (const float*)d_in[8];
    const float* W2       = (const float*)d_in[9];
    const float* b2       = (const float*)d_in[10];
    const float* W_temb   = (const float*)d_in[11];
    float* out = (float*)d_out;

    const int E = in_sizes[3];
    const int N = in_sizes[4];
    const int prep_blocks = (N + 511) / 512;
    const int edge_blocks = (E / 2 + 255) / 256;

    fusedA_kernel<<<64 + prep_blocks, 512>>>(t, W1, b1, W2, b2, x, ntype, N);
    scatterB_kernel<<<8 + edge_blocks, 256>>>(ei, etype, W_temb, E);
    gemv_kernel<<<(N / 2 + 127) / 128, 128>>>(W_conv, batch_id, out, N);
}